// round 1
// baseline (speedup 1.0000x reference)
#include <cuda_runtime.h>

#define T_STEPS 4096
#define H       1024
#define NG      7
#define GW      (NG * H)      // 7168 gate columns
#define KROWS   33
#define NB      128           // persistent blocks (1 per SM, <=148)
#define NT      256           // threads per block (8 warps)
#define UNITS   8             // hidden units per block
#define COLS    (UNITS * NG)  // 56 gate columns per block
#define KSUB    11            // emb rows per precompute block (3*11 = 33)

// -------- device scratch (no allocations allowed) --------
__device__ float    g_pre[KROWS * GW];   // precomputed input contribution + bias
__device__ float    g_h[2 * H];          // double-buffered h_d
__device__ unsigned g_bar;               // grid barrier counter

// -------- helpers --------
__device__ __forceinline__ unsigned ld_acquire_u32(const unsigned* p) {
    unsigned v;
    asm volatile("ld.acquire.gpu.u32 %0, [%1];" : "=r"(v) : "l"(p));
    return v;
}
__device__ __forceinline__ float sigmoidf_(float x) {
    return __fdividef(1.0f, 1.0f + __expf(-x));
}
__device__ __forceinline__ float tanhf_(float x) {
    return 1.0f - __fdividef(2.0f, __expf(2.0f * x) + 1.0f);
}
__device__ __forceinline__ float softplusf_(float x) {
    return fmaxf(x, 0.0f) + __logf(1.0f + __expf(-fabsf(x)));
}

// -------- kernel 0: reset persistent state (graph-replay determinism) --------
__global__ void init_kernel() {
    int i = blockIdx.x * blockDim.x + threadIdx.x;
    if (i == 0) g_bar = 0u;
    if (i < 2 * H) g_h[i] = 0.0f;
}

// -------- kernel 1: pre[k][j] = emb[k] @ W_top[:,j] + b_r[j] --------
__global__ void pre_kernel(const float* __restrict__ w_r,
                           const float* __restrict__ b_r,
                           const float* __restrict__ emb) {
    __shared__ float es[KSUB * H];
    const int j  = blockIdx.x * NT + threadIdx.x;   // gate column
    const int k0 = blockIdx.y * KSUB;               // emb row base

    for (int idx = threadIdx.x; idx < KSUB * H; idx += NT)
        es[idx] = emb[k0 * H + idx];
    __syncthreads();

    float acc[KSUB];
#pragma unroll
    for (int k = 0; k < KSUB; ++k) acc[k] = 0.0f;

    const float4* es4 = (const float4*)es;
    for (int i4 = 0; i4 < H / 4; ++i4) {
        const int i = i4 * 4;
        const float w0 = w_r[(i + 0) * GW + j];
        const float w1 = w_r[(i + 1) * GW + j];
        const float w2 = w_r[(i + 2) * GW + j];
        const float w3 = w_r[(i + 3) * GW + j];
#pragma unroll
        for (int k = 0; k < KSUB; ++k) {
            float4 e = es4[k * (H / 4) + i4];
            acc[k] = fmaf(w0, e.x, fmaf(w1, e.y, fmaf(w2, e.z, fmaf(w3, e.w, acc[k]))));
        }
    }
    const float b = b_r[j];
#pragma unroll
    for (int k = 0; k < KSUB; ++k)
        g_pre[(k0 + k) * GW + j] = acc[k] + b;
}

// -------- kernel 2: persistent sequential CTLSTM --------
__global__ void __launch_bounds__(NT, 1)
ctlstm_kernel(const int*   __restrict__ event,
              const float* __restrict__ duration,
              const float* __restrict__ w_r,
              float*       __restrict__ out) {
    extern __shared__ float Ws[];   // [COLS][H] : per-block recurrent weight slice

    const int tid  = threadIdx.x;
    const int lane = tid & 31;
    const int w    = tid >> 5;                  // warp id 0..7 -> local unit
    const int n    = blockIdx.x * UNITS + w;    // global hidden unit

    // One-time load of this block's 56 weight columns into SMEM.
    // Ws[c*H + i] = W_h[i][gate g, unit wu], c = wu*NG + g
    for (int idx = tid; idx < COLS * H; idx += NT) {
        const int c  = idx >> 10;
        const int i  = idx & (H - 1);
        const int wu = c / NG;
        const int g  = c % NG;
        Ws[idx] = w_r[(H + i) * GW + g * H + blockIdx.x * UNITS + wu];
    }
    __syncthreads();

    const float4* Wv = (const float4*)Ws + (w * NG) * (H / 4);

    float c_st = 0.0f, cb_st = 0.0f;  // per-unit recurrent state (valid in all lanes)

    for (int t = 0; t < T_STEPS; ++t) {
        if (t > 0) {
            if (tid == 0) {
                const unsigned tgt = (unsigned)NB * (unsigned)t;
                while (ld_acquire_u32(&g_bar) < tgt) { }
            }
            __syncthreads();
        }

        const int   e = __ldg(&event[t]);
        const float d = __ldg(&duration[t]);

        // broadcast h_d from L2 (bypass L1 — other SMs wrote it)
        const float4* hp = (const float4*)(g_h + (t & 1) * H);
        float4 hx[8];
#pragma unroll
        for (int k = 0; k < 8; ++k) hx[k] = __ldcg(&hp[lane + 32 * k]);

        float acc[NG];
#pragma unroll
        for (int g = 0; g < NG; ++g) acc[g] = 0.0f;

#pragma unroll
        for (int k = 0; k < 8; ++k) {
            const float4 h4 = hx[k];
#pragma unroll
            for (int g = 0; g < NG; ++g) {
                const float4 w4 = Wv[g * (H / 4) + lane + 32 * k];
                acc[g] = fmaf(w4.x, h4.x,
                         fmaf(w4.y, h4.y,
                         fmaf(w4.z, h4.z,
                         fmaf(w4.w, h4.w, acc[g]))));
            }
        }

        // warp reduction (all lanes end with full sums)
#pragma unroll
        for (int g = 0; g < NG; ++g) {
#pragma unroll
            for (int o = 16; o > 0; o >>= 1)
                acc[g] += __shfl_xor_sync(0xffffffffu, acc[g], o);
        }

        const float* prow = g_pre + (size_t)e * GW + n;
        float gate[NG];
#pragma unroll
        for (int g = 0; g < NG; ++g)
            gate[g] = acc[g] + __ldg(&prow[g * H]);

        const float gi  = sigmoidf_(gate[0]);
        const float gf  = sigmoidf_(gate[1]);
        const float gz  = tanhf_(gate[2]);
        const float go  = sigmoidf_(gate[3]);
        const float gib = sigmoidf_(gate[4]);
        const float gfb = sigmoidf_(gate[5]);
        const float gdl = softplusf_(gate[6]);

        c_st  = gf  * c_st  + gi  * gz;
        cb_st = gfb * cb_st + gib * gz;
        const float h_t = go * tanhf_(c_st);
        const float cd  = cb_st + (c_st - cb_st) * __expf(-gdl * d);
        const float h_d = go * tanhf_(cd);

        if (lane == 0) {
            const int TH = T_STEPS * H;
            float* o0 = out + t * H + n;
            o0[0 * TH] = h_t;
            o0[1 * TH] = c_st;
            o0[2 * TH] = cb_st;
            o0[3 * TH] = go;
            o0[4 * TH] = gdl;
            g_h[((t + 1) & 1) * H + n] = h_d;
        }

        __syncthreads();                 // all warps published their h_d
        if (tid == 0) {
            __threadfence();             // release h_d stores device-wide
            atomicAdd(&g_bar, 1u);       // arrive
        }
    }
}

// -------- launch --------
extern "C" void kernel_launch(void* const* d_in, const int* in_sizes, int n_in,
                              void* d_out, int out_size) {
    const int*   event    = (const int*)  d_in[0];
    const float* duration = (const float*)d_in[1];
    const float* w_r      = (const float*)d_in[2];
    const float* b_r      = (const float*)d_in[3];
    const float* emb      = (const float*)d_in[4];
    float*       out      = (float*)d_out;

    (void)in_sizes; (void)n_in; (void)out_size;

    const size_t smem = (size_t)COLS * H * sizeof(float);  // 229376 B
    cudaFuncSetAttribute(ctlstm_kernel,
                         cudaFuncAttributeMaxDynamicSharedMemorySize,
                         (int)smem);

    init_kernel<<<8, 256>>>();
    pre_kernel<<<dim3(GW / NT, KROWS / KSUB), NT>>>(w_r, b_r, emb);
    ctlstm_kernel<<<NB, NT, smem>>>(event, duration, w_r, out);
}